// round 15
// baseline (speedup 1.0000x reference)
#include <cuda_runtime.h>
#include <cstdint>

#define BB   16
#define CC   32
#define HH   256
#define WW   256
#define T2   8
#define NT   16
#define NHC  32               // half-chunks (8 rows)
#define NQC  64               // quarter-chunks (4 rows each)
#define FIELD (HH*WW)
#define BT   (BB*T2)

#define SMEM_XBUF (2*CC*WW*4)             // 65536 B: double-buffered x row tile
#define SMEM_K1   SMEM_XBUF

typedef unsigned long long u64;

// ---------------- scratch (no cudaMalloc allowed) ----------------
__device__ __align__(256) float g_w1 [BT*FIELD];
__device__ __align__(256) float g_gv2[BT*FIELD];
__device__ __align__(256) float g_Sh [BT*3*NQC*WW];   // qc colsums (w3,w3p,w2p) -> suffix-excl after kS
__device__ __align__(256) float g_S3 [BT*NQC*WW];     // qc colsums of gv2 -> prefix-excl after kS2
__device__ u64 g_apk[T2*6*CC];                        // packed alphas (staging)
__constant__ u64 c_al[T2*6*CC];                       // packed alphas (constant port)

// ---------------- f32x2 helpers ----------------
__device__ __forceinline__ u64 fma2(u64 a, u64 b, u64 c) {
    u64 d; asm("fma.rn.f32x2 %0, %1, %2, %3;" : "=l"(d) : "l"(a), "l"(b), "l"(c)); return d;
}
__device__ __forceinline__ u64 add2(u64 a, u64 b) {
    u64 d; asm("add.rn.f32x2 %0, %1, %2;" : "=l"(d) : "l"(a), "l"(b)); return d;
}
__device__ __forceinline__ u64 pack2(float lo, float hi) {
    u64 r; asm("mov.b64 %0, {%1, %2};" : "=l"(r) : "f"(lo), "f"(hi)); return r;
}
__device__ __forceinline__ float2 unpack2(u64 v) {
    float2 f; asm("mov.b64 {%0, %1}, %2;" : "=f"(f.x), "=f"(f.y) : "l"(v)); return f;
}
__device__ __forceinline__ void LD8(float* v, const float* p) {
    float4 a = *(const float4*)p, b = *(const float4*)(p + 4);
    v[0]=a.x; v[1]=a.y; v[2]=a.z; v[3]=a.w; v[4]=b.x; v[5]=b.y; v[6]=b.z; v[7]=b.w;
}
__device__ __forceinline__ void ST8(float* p, const float* v) {
    *(float4*)p       = make_float4(v[0],v[1],v[2],v[3]);
    *(float4*)(p + 4) = make_float4(v[4],v[5],v[6],v[7]);
}
__device__ __forceinline__ void UNP8(float* v, const u64* q) {
    #pragma unroll
    for (int j = 0; j < 4; j++) {
        float2 u = unpack2(q[j]); v[2*j] = u.x; v[2*j+1] = u.y;
    }
}

// ---------------- cp.async helpers ----------------
__device__ __forceinline__ uint32_t smem_u32(const void* p) {
    uint32_t a;
    asm("{ .reg .u64 t; cvta.to.shared.u64 t, %1; cvt.u32.u64 %0, t; }"
        : "=r"(a) : "l"(p));
    return a;
}
#define CP16(dst, src) \
    asm volatile("cp.async.ca.shared.global [%0], [%1], 16;" :: "r"(dst), "l"(src))
#define CP_COMMIT() asm volatile("cp.async.commit_group;")
#define CP_WAIT(n)  asm volatile("cp.async.wait_group %0;" :: "n"(n))

// ---------------- warp scan: 256 elems, 8 per lane (warp-local) ----------------
__device__ __forceinline__ float wscan8(const float* v, float* incl) {
    float r = 0.f; float tmp[8];
    #pragma unroll
    for (int i = 0; i < 8; i++) { r += v[i]; tmp[i] = r; }
    float s = r;
    const int lane = threadIdx.x & 31;
    #pragma unroll
    for (int d = 1; d < 32; d <<= 1) {
        float n = __shfl_up_sync(0xffffffffu, s, d);
        if (lane >= d) s += n;
    }
    float excl = s - r;
    #pragma unroll
    for (int i = 0; i < 8; i++) incl[i] = tmp[i] + excl;
    return __shfl_sync(0xffffffffu, s, 31);
}

// =====================================================================
// K0: pack alphas duplicated into f32x2 pairs
// field order: 0=a1 1=a2 2=a3 3=a1p 4=a2p 5=a3p
// =====================================================================
__global__ void k0_pack(const float* __restrict__ a1,  const float* __restrict__ a2,
                        const float* __restrict__ a3,  const float* __restrict__ a1p,
                        const float* __restrict__ a2p, const float* __restrict__ a3p)
{
    int i = blockIdx.x * 256 + threadIdx.x;          // T2*6*CC = 1536
    if (i >= T2 * 6 * CC) return;
    int c = i % CC, f = (i / CC) % 6, t = i / (6 * CC);
    const float* p = (f == 0) ? a1 : (f == 1) ? a2 : (f == 2) ? a3
                   : (f == 3) ? a1p : (f == 4) ? a2p : a3p;
    float v = p[t * CC + c];
    g_apk[(t * 6 + f) * CC + c] = pack2(v, v);
}

// =====================================================================
// KAB: raw quarterchunk colsums contracted with alphas (all 8 trees).
// CTA = halfchunk: 2 rowgroups x 64 lanes x float4. grid = (NHC, BB).
// =====================================================================
__global__ void __launch_bounds__(128) kAB_colsum(const float* __restrict__ x)
{
    __shared__ __align__(16) u64 s_alB[CC][24];   // slot = k*8 + t
    const int tid = threadIdx.x;
    const int rg  = tid >> 6;
    const int l   = tid & 63;
    const int hc  = blockIdx.x;
    const int b   = blockIdx.y;
    const int qc  = hc * 2 + rg;
    const int col = l * 4;

    for (int i = tid; i < CC * 24; i += 128) {
        int slot = i % 24, c = i / 24;
        int k = slot / 8, t = slot % 8;
        int f = (k == 0) ? 2 : (k == 1) ? 5 : 4;   // a3, a3p, a2p
        s_alB[c][slot] = g_apk[(t * 6 + f) * CC + c];
    }
    __syncthreads();

    u64 acc[24][2];
    #pragma unroll
    for (int s = 0; s < 24; s++) { acc[s][0] = 0ull; acc[s][1] = 0ull; }

    #pragma unroll 2
    for (int c = 0; c < CC; c++) {
        const float4* xp = (const float4*)(x
            + ((size_t)(b * CC + c) * HH + qc * 4) * WW + col);
        u64 s01 = 0ull, s23 = 0ull;
        #pragma unroll
        for (int r = 0; r < 4; r++) {
            float4 v = xp[r * (WW / 4)];
            s01 = add2(s01, pack2(v.x, v.y));
            s23 = add2(s23, pack2(v.z, v.w));
        }
        #pragma unroll
        for (int j = 0; j < 12; j++) {
            ulonglong2 p = *(const ulonglong2*)&s_alB[c][2 * j];
            acc[2*j][0]   = fma2(s01, p.x, acc[2*j][0]);
            acc[2*j][1]   = fma2(s23, p.x, acc[2*j][1]);
            acc[2*j+1][0] = fma2(s01, p.y, acc[2*j+1][0]);
            acc[2*j+1][1] = fma2(s23, p.y, acc[2*j+1][1]);
        }
    }

    #pragma unroll
    for (int k = 0; k < 3; k++)
        #pragma unroll
        for (int t = 0; t < T2; t++) {
            int s = k * 8 + t;
            float2 v0 = unpack2(acc[s][0]), v1 = unpack2(acc[s][1]);
            size_t o = (((size_t)(b * T2 + t) * 3 + k) * NQC + qc) * WW + col;
            *(float4*)&g_Sh[o] = make_float4(v0.x, v0.y, v1.x, v1.y);
        }
}

// =====================================================================
// KS: in-place exclusive SUFFIX sum of g_Sh along qc (per bt,k,w column)
// =====================================================================
__global__ void kS_suffix()
{
    int gid = blockIdx.x * 128 + threadIdx.x;   // BT*3*WW = 98304
    int w   = gid & (WW - 1);
    int ktb = gid >> 8;
    float* base = g_Sh + (size_t)ktb * NQC * WW + w;
    float v[NQC];
    #pragma unroll
    for (int j = 0; j < NQC; j++) v[j] = base[(size_t)j * WW];
    float s = 0.f;
    #pragma unroll
    for (int j = NQC - 1; j >= 0; j--) {
        base[(size_t)j * WW] = s;
        s += v[j];
    }
}

// =====================================================================
// KS2: in-place exclusive PREFIX sum of g_S3 along qc
// =====================================================================
__global__ void kS2_prefix()
{
    int gid = blockIdx.x * 128 + threadIdx.x;   // BT*WW = 32768
    int w   = gid & (WW - 1);
    int bt  = gid >> 8;
    float* base = g_S3 + (size_t)bt * NQC * WW + w;
    float v[NQC];
    #pragma unroll
    for (int j = 0; j < NQC; j++) v[j] = base[(size_t)j * WW];
    float s = 0.f;
    #pragma unroll
    for (int j = 0; j < NQC; j++) {
        base[(size_t)j * WW] = s;
        s += v[j];
    }
}

// =====================================================================
// K1_FUSED v6: cp.async-staged x + CONSTANT-PORT alphas.
// CTA = (quarterchunk, batch), 256 thr = 8 warps = 8 trees.
// x row tile (32ch x 256w = 32KB) staged via cp.async, double-buffered.
// Alphas read from __constant__ (warp-uniform index -> constant port,
// off the saturated L1/smem crossbar). smem = 64KB (x buffers only).
// Emits: cherry -> out, gv2, w1, S3 (raw qc colsums of gv2).
// grid = (NQC, BB) = 1024 CTAs.
// =====================================================================
__global__ void __launch_bounds__(256, 2) k1_fused(const float* __restrict__ x,
                                                   float* __restrict__ out)
{
    extern __shared__ __align__(16) char smem[];
    float* s_x = (float*)smem;                         // [2][CC][WW]

    const int tid  = threadIdx.x;
    const int t    = tid >> 5;         // warp = tree
    const int lane = tid & 31;
    const int col  = lane * 8;
    const int qc   = blockIdx.x;
    const int b    = blockIdx.y;
    const int bt   = b * T2 + t;

    const uint32_t s_x_u32 = smem_u32(s_x);

    // ---- init states from suffix-excl Sh (fwd/rev excl scans along w) ----
    float a3[8], p3[8], p2[8], cs[8], incl[8];
    {
        float v[8];
        const size_t sb = ((size_t)bt * 3) * NQC * WW + (size_t)qc * WW + col;
        LD8(v, g_Sh + sb);
        wscan8(v, incl);
        #pragma unroll
        for (int i = 0; i < 8; i++) a3[i] = incl[i] - v[i];
        LD8(v, g_Sh + sb + (size_t)NQC * WW);
        wscan8(v, incl);
        #pragma unroll
        for (int i = 0; i < 8; i++) p3[i] = incl[i] - v[i];
        LD8(v, g_Sh + sb + 2 * (size_t)NQC * WW);
        float tot = wscan8(v, incl);
        #pragma unroll
        for (int i = 0; i < 8; i++) p2[i] = tot - incl[i];
        #pragma unroll
        for (int i = 0; i < 8; i++) cs[i] = 0.f;
    }

    // ---- staging: thread copies 8x16B chunks; chunk i: c=i/64, col16=i%64 ----
    const char* xg = (const char*)(x + (size_t)b * CC * FIELD);
    auto stage = [&](int r, int bi) {
        const int h = qc * 4 + r;
        #pragma unroll
        for (int j = 0; j < 8; j++) {
            int idx  = tid + 256 * j;               // 0..2047
            int c    = idx >> 6;
            int c16  = idx & 63;
            uint32_t dst = s_x_u32 + (uint32_t)(bi * SMEM_XBUF / 2 + c * (WW * 4) + c16 * 16);
            const char* src = xg + ((size_t)c * FIELD + (size_t)h * WW) * 4 + c16 * 16;
            CP16(dst, src);
        }
    };

    stage(3, 0);
    CP_COMMIT();

    const int alb = t * 6 * CC;    // warp-uniform alpha base

    // ---- 4 rows, bottom-up; k = 3 - r ----
    #pragma unroll 1
    for (int r = 3; r >= 0; r--) {
        const int k = 3 - r;
        if (r > 0) {
            stage(r - 1, (k + 1) & 1);   // target buffer consumed 2 iters ago
            CP_COMMIT();
            CP_WAIT(1);                  // wait for row r's group
        } else {
            CP_WAIT(0);
        }
        __syncthreads();

        const float* sx = s_x + (size_t)(k & 1) * CC * WW + col;
        const int h = qc * 4 + r;

        u64 acc[6][4];
        #pragma unroll
        for (int f = 0; f < 6; f++)
            #pragma unroll
            for (int j = 0; j < 4; j++) acc[f][j] = 0ull;

        #pragma unroll 4
        for (int c = 0; c < CC; c++) {
            float4 v0 = *(const float4*)(sx + c * WW);
            float4 v1 = *(const float4*)(sx + c * WW + 4);
            u64 x01 = pack2(v0.x, v0.y);
            u64 x23 = pack2(v0.z, v0.w);
            u64 x45 = pack2(v1.x, v1.y);
            u64 x67 = pack2(v1.z, v1.w);
            // alphas from constant memory (warp-uniform -> constant port)
            u64 q0 = c_al[alb + 0 * CC + c];
            u64 q1 = c_al[alb + 1 * CC + c];
            u64 q2 = c_al[alb + 2 * CC + c];
            u64 q3 = c_al[alb + 3 * CC + c];
            u64 q4 = c_al[alb + 4 * CC + c];
            u64 q5 = c_al[alb + 5 * CC + c];
            acc[0][0] = fma2(x01, q0, acc[0][0]);
            acc[0][1] = fma2(x23, q0, acc[0][1]);
            acc[0][2] = fma2(x45, q0, acc[0][2]);
            acc[0][3] = fma2(x67, q0, acc[0][3]);
            acc[1][0] = fma2(x01, q1, acc[1][0]);
            acc[1][1] = fma2(x23, q1, acc[1][1]);
            acc[1][2] = fma2(x45, q1, acc[1][2]);
            acc[1][3] = fma2(x67, q1, acc[1][3]);
            acc[2][0] = fma2(x01, q2, acc[2][0]);
            acc[2][1] = fma2(x23, q2, acc[2][1]);
            acc[2][2] = fma2(x45, q2, acc[2][2]);
            acc[2][3] = fma2(x67, q2, acc[2][3]);
            acc[3][0] = fma2(x01, q3, acc[3][0]);
            acc[3][1] = fma2(x23, q3, acc[3][1]);
            acc[3][2] = fma2(x45, q3, acc[3][2]);
            acc[3][3] = fma2(x67, q3, acc[3][3]);
            acc[4][0] = fma2(x01, q4, acc[4][0]);
            acc[4][1] = fma2(x23, q4, acc[4][1]);
            acc[4][2] = fma2(x45, q4, acc[4][2]);
            acc[4][3] = fma2(x67, q4, acc[4][3]);
            acc[5][0] = fma2(x01, q5, acc[5][0]);
            acc[5][1] = fma2(x23, q5, acc[5][1]);
            acc[5][2] = fma2(x45, q5, acc[5][2]);
            acc[5][3] = fma2(x67, q5, acc[5][3]);
        }

        const size_t fb = (size_t)bt * FIELD + (size_t)h * WW + col;
        float v[8];

        // gv2 = rev-excl-w-scan(w2 * a3); accumulate colsum
        UNP8(v, acc[1]);
        #pragma unroll
        for (int i = 0; i < 8; i++) v[i] *= a3[i];
        float tot = wscan8(v, incl);
        float gv[8];
        #pragma unroll
        for (int i = 0; i < 8; i++) { gv[i] = tot - incl[i]; cs[i] += gv[i]; }
        ST8(g_gv2 + fb, gv);

        // w1
        UNP8(v, acc[0]);
        ST8(g_w1 + fb, v);

        // cherry = w1p * p3 * p2 (strict-below states)
        UNP8(v, acc[3]);
        #pragma unroll
        for (int i = 0; i < 8; i++) v[i] *= p3[i] * p2[i];
        ST8(out + ((size_t)(b * NT + T2 + t)) * FIELD + (size_t)h * WW + col, v);

        // state updates
        UNP8(v, acc[2]);                    // w3
        wscan8(v, incl);
        #pragma unroll
        for (int i = 0; i < 8; i++) a3[i] += incl[i] - v[i];

        UNP8(v, acc[5]);                    // w3p
        wscan8(v, incl);
        #pragma unroll
        for (int i = 0; i < 8; i++) p3[i] += incl[i] - v[i];

        UNP8(v, acc[4]);                    // w2p
        tot = wscan8(v, incl);
        #pragma unroll
        for (int i = 0; i < 8; i++) p2[i] += tot - incl[i];

        __syncthreads();   // protect buffer reuse by next iteration's stage
    }

    ST8(g_S3 + ((size_t)bt * NQC + qc) * WW + col, cs);
}

// =====================================================================
// KD: top-down. linear = w1 * strict-north colsum of gv2.
// One warp per (qc,t,b) = 8192 warps; init from prefix-excl S3.
// =====================================================================
__global__ void __launch_bounds__(128) kD_topdown(float* __restrict__ out)
{
    const int wid  = threadIdx.x >> 5;
    const int lane = threadIdx.x & 31;
    const int gw   = blockIdx.x * 4 + wid;
    const int qc   =  gw        & 63;
    const int t    = (gw >> 6)  & 7;
    const int b    =  gw >> 9;
    const int bt   = b * T2 + t;
    const int col  = lane * 8;

    float va[8];
    LD8(va, g_S3 + ((size_t)bt * NQC + qc) * WW + col);   // prefix-excl

    const size_t fbase = (size_t)bt * FIELD + (size_t)(qc * 4) * WW + col;
    const size_t obase = ((size_t)(b * NT + t)) * FIELD + (size_t)(qc * 4) * WW + col;

    float w1b[8], gvb[8];
    LD8(w1b, g_w1 + fbase);
    LD8(gvb, g_gv2 + fbase);

    #pragma unroll
    for (int r = 0; r < 4; r++) {
        float w1n[8], gvn[8];
        if (r < 3) {
            LD8(w1n, g_w1  + fbase + (size_t)(r + 1) * WW);
            LD8(gvn, g_gv2 + fbase + (size_t)(r + 1) * WW);
        }
        float o[8];
        #pragma unroll
        for (int i = 0; i < 8; i++) o[i] = w1b[i] * va[i];
        ST8(out + obase + (size_t)r * WW, o);
        #pragma unroll
        for (int i = 0; i < 8; i++) va[i] += gvb[i];
        if (r < 3) {
            #pragma unroll
            for (int i = 0; i < 8; i++) { w1b[i] = w1n[i]; gvb[i] = gvn[i]; }
        }
    }
}

// =====================================================================
extern "C" void kernel_launch(void* const* d_in, const int* in_sizes, int n_in,
                              void* d_out, int out_size)
{
    const float* x   = (const float*)d_in[0];
    const float* a1  = (const float*)d_in[1];
    const float* a2  = (const float*)d_in[2];
    const float* a3  = (const float*)d_in[3];
    const float* a1p = (const float*)d_in[4];
    const float* a2p = (const float*)d_in[5];
    const float* a3p = (const float*)d_in[6];
    float* out = (float*)d_out;

    static bool attr_set = false;
    if (!attr_set) {
        cudaFuncSetAttribute(k1_fused,
                             cudaFuncAttributeMaxDynamicSharedMemorySize, SMEM_K1);
        attr_set = true;
    }

    k0_pack<<<6, 256>>>(a1, a2, a3, a1p, a2p, a3p);

    // Stage packed alphas into the constant bank (validated R5/R10).
    void* src = nullptr; void* dst = nullptr;
    cudaGetSymbolAddress(&src, g_apk);
    cudaGetSymbolAddress(&dst, c_al);
    cudaMemcpyAsync(dst, src, sizeof(u64) * T2 * 6 * CC,
                    cudaMemcpyDeviceToDevice, 0);

    dim3 gAB(NHC, BB);                          // (32, 16)
    kAB_colsum<<<gAB, 128>>>(x);

    kS_suffix<<<BT * 3 * WW / 128, 128>>>();    // 768 blocks

    dim3 gC(NQC, BB);                           // (64, 16) = 1024 CTAs
    k1_fused<<<gC, 256, SMEM_K1>>>(x, out);

    kS2_prefix<<<BT * WW / 128, 128>>>();       // 256 blocks

    kD_topdown<<<BT * NQC / 4, 128>>>(out);     // 2048 blocks
}

// round 16
// speedup vs baseline: 3.7080x; 3.7080x over previous
#include <cuda_runtime.h>
#include <cstdint>

#define BB   16
#define CC   32
#define HH   256
#define WW   256
#define T2   8
#define NT   16
#define NHC  32               // half-chunks (8 rows)
#define NQC  64               // quarter-chunks (4 rows each)
#define FIELD (HH*WW)
#define BT   (BB*T2)

#define SMEM_XBUF (2*CC*WW*4)             // 65536 B: double-buffered x row tile
#define SMEM_ALPH (T2*CC*6*8)             // 12288 B alphas
#define SMEM_MBAR (SMEM_XBUF + SMEM_ALPH) // mbarriers at 77824
#define SMEM_K1   (SMEM_MBAR + 16)        // 77840 B

typedef unsigned long long u64;

// ---------------- scratch (no cudaMalloc allowed) ----------------
__device__ __align__(256) float g_w1 [BT*FIELD];
__device__ __align__(256) float g_gv2[BT*FIELD];
__device__ __align__(256) float g_Sh [BT*3*NQC*WW];   // qc colsums (w3,w3p,w2p) -> suffix-excl after kS
__device__ __align__(256) float g_S3 [BT*NQC*WW];     // qc colsums of gv2 -> prefix-excl after kS2
__device__ u64 g_apk[T2*6*CC];                        // packed alphas

// ---------------- f32x2 helpers ----------------
__device__ __forceinline__ u64 fma2(u64 a, u64 b, u64 c) {
    u64 d; asm("fma.rn.f32x2 %0, %1, %2, %3;" : "=l"(d) : "l"(a), "l"(b), "l"(c)); return d;
}
__device__ __forceinline__ u64 add2(u64 a, u64 b) {
    u64 d; asm("add.rn.f32x2 %0, %1, %2;" : "=l"(d) : "l"(a), "l"(b)); return d;
}
__device__ __forceinline__ u64 pack2(float lo, float hi) {
    u64 r; asm("mov.b64 %0, {%1, %2};" : "=l"(r) : "f"(lo), "f"(hi)); return r;
}
__device__ __forceinline__ float2 unpack2(u64 v) {
    float2 f; asm("mov.b64 {%0, %1}, %2;" : "=f"(f.x), "=f"(f.y) : "l"(v)); return f;
}
__device__ __forceinline__ void LD8(float* v, const float* p) {
    float4 a = *(const float4*)p, b = *(const float4*)(p + 4);
    v[0]=a.x; v[1]=a.y; v[2]=a.z; v[3]=a.w; v[4]=b.x; v[5]=b.y; v[6]=b.z; v[7]=b.w;
}
__device__ __forceinline__ void ST8(float* p, const float* v) {
    *(float4*)p       = make_float4(v[0],v[1],v[2],v[3]);
    *(float4*)(p + 4) = make_float4(v[4],v[5],v[6],v[7]);
}
__device__ __forceinline__ void UNP8(float* v, const u64* q) {
    #pragma unroll
    for (int j = 0; j < 4; j++) {
        float2 u = unpack2(q[j]); v[2*j] = u.x; v[2*j+1] = u.y;
    }
}

// ---------------- async-bulk + mbarrier helpers ----------------
__device__ __forceinline__ uint32_t smem_u32(const void* p) {
    uint32_t a;
    asm("{ .reg .u64 t; cvta.to.shared.u64 t, %1; cvt.u32.u64 %0, t; }"
        : "=r"(a) : "l"(p));
    return a;
}
#define MBAR_INIT(mbar, cnt) \
    asm volatile("mbarrier.init.shared.b64 [%0], %1;" :: "r"(mbar), "r"(cnt) : "memory")
#define MBAR_EXPECT_TX(mbar, bytes) \
    asm volatile("mbarrier.arrive.expect_tx.shared.b64 _, [%0], %1;" \
                 :: "r"(mbar), "r"(bytes) : "memory")
#define BULK_CP(dst, src, bytes, mbar) \
    asm volatile("cp.async.bulk.shared::cta.global.mbarrier::complete_tx::bytes " \
                 "[%0], [%1], %2, [%3];" \
                 :: "r"(dst), "l"(src), "r"(bytes), "r"(mbar) : "memory")
#define FENCE_PROXY_ASYNC() asm volatile("fence.proxy.async.shared::cta;" ::: "memory")
#define MBAR_WAIT(mbar, parity) do { \
    uint32_t _m = (mbar); uint32_t _p = (parity); uint32_t _done; \
    asm volatile("{\n\t.reg .pred p;\n\t" \
        "mbarrier.try_wait.parity.acquire.cta.shared::cta.b64 p, [%1], %2;\n\t" \
        "selp.b32 %0, 1, 0, p;\n\t}" : "=r"(_done) : "r"(_m), "r"(_p) : "memory"); \
    if (!_done) { \
        asm volatile("{\n\t.reg .pred P1;\n\t" \
            "WAIT_LOOP_%=:\n\t" \
            "mbarrier.try_wait.parity.acquire.cta.shared::cta.b64 P1, [%0], %1, 0x989680;\n\t" \
            "@P1 bra.uni WAIT_DONE_%=;\n\t" \
            "bra.uni WAIT_LOOP_%=;\n\t" \
            "WAIT_DONE_%=:\n\t}" :: "r"(_m), "r"(_p) : "memory"); \
    } \
} while(0)

// ---------------- warp scan: 256 elems, 8 per lane (warp-local) ----------------
__device__ __forceinline__ float wscan8(const float* v, float* incl) {
    float r = 0.f; float tmp[8];
    #pragma unroll
    for (int i = 0; i < 8; i++) { r += v[i]; tmp[i] = r; }
    float s = r;
    const int lane = threadIdx.x & 31;
    #pragma unroll
    for (int d = 1; d < 32; d <<= 1) {
        float n = __shfl_up_sync(0xffffffffu, s, d);
        if (lane >= d) s += n;
    }
    float excl = s - r;
    #pragma unroll
    for (int i = 0; i < 8; i++) incl[i] = tmp[i] + excl;
    return __shfl_sync(0xffffffffu, s, 31);
}

// =====================================================================
// K0: pack alphas duplicated into f32x2 pairs
// field order: 0=a1 1=a2 2=a3 3=a1p 4=a2p 5=a3p
// =====================================================================
__global__ void k0_pack(const float* __restrict__ a1,  const float* __restrict__ a2,
                        const float* __restrict__ a3,  const float* __restrict__ a1p,
                        const float* __restrict__ a2p, const float* __restrict__ a3p)
{
    int i = blockIdx.x * 256 + threadIdx.x;          // T2*6*CC = 1536
    if (i >= T2 * 6 * CC) return;
    int c = i % CC, f = (i / CC) % 6, t = i / (6 * CC);
    const float* p = (f == 0) ? a1 : (f == 1) ? a2 : (f == 2) ? a3
                   : (f == 3) ? a1p : (f == 4) ? a2p : a3p;
    float v = p[t * CC + c];
    g_apk[(t * 6 + f) * CC + c] = pack2(v, v);
}

// =====================================================================
// KAB: raw quarterchunk colsums contracted with alphas (all 8 trees).
// CTA = halfchunk: 2 rowgroups x 64 lanes x float4. grid = (NHC, BB).
// =====================================================================
__global__ void __launch_bounds__(128) kAB_colsum(const float* __restrict__ x)
{
    __shared__ __align__(16) u64 s_alB[CC][24];   // slot = k*8 + t
    const int tid = threadIdx.x;
    const int rg  = tid >> 6;
    const int l   = tid & 63;
    const int hc  = blockIdx.x;
    const int b   = blockIdx.y;
    const int qc  = hc * 2 + rg;
    const int col = l * 4;

    for (int i = tid; i < CC * 24; i += 128) {
        int slot = i % 24, c = i / 24;
        int k = slot / 8, t = slot % 8;
        int f = (k == 0) ? 2 : (k == 1) ? 5 : 4;   // a3, a3p, a2p
        s_alB[c][slot] = g_apk[(t * 6 + f) * CC + c];
    }
    __syncthreads();

    u64 acc[24][2];
    #pragma unroll
    for (int s = 0; s < 24; s++) { acc[s][0] = 0ull; acc[s][1] = 0ull; }

    #pragma unroll 2
    for (int c = 0; c < CC; c++) {
        const float4* xp = (const float4*)(x
            + ((size_t)(b * CC + c) * HH + qc * 4) * WW + col);
        u64 s01 = 0ull, s23 = 0ull;
        #pragma unroll
        for (int r = 0; r < 4; r++) {
            float4 v = xp[r * (WW / 4)];
            s01 = add2(s01, pack2(v.x, v.y));
            s23 = add2(s23, pack2(v.z, v.w));
        }
        #pragma unroll
        for (int j = 0; j < 12; j++) {
            ulonglong2 p = *(const ulonglong2*)&s_alB[c][2 * j];
            acc[2*j][0]   = fma2(s01, p.x, acc[2*j][0]);
            acc[2*j][1]   = fma2(s23, p.x, acc[2*j][1]);
            acc[2*j+1][0] = fma2(s01, p.y, acc[2*j+1][0]);
            acc[2*j+1][1] = fma2(s23, p.y, acc[2*j+1][1]);
        }
    }

    #pragma unroll
    for (int k = 0; k < 3; k++)
        #pragma unroll
        for (int t = 0; t < T2; t++) {
            int s = k * 8 + t;
            float2 v0 = unpack2(acc[s][0]), v1 = unpack2(acc[s][1]);
            size_t o = (((size_t)(b * T2 + t) * 3 + k) * NQC + qc) * WW + col;
            *(float4*)&g_Sh[o] = make_float4(v0.x, v0.y, v1.x, v1.y);
        }
}

// =====================================================================
// KS: in-place exclusive SUFFIX sum of g_Sh along qc (per bt,k,w column)
// =====================================================================
__global__ void kS_suffix()
{
    int gid = blockIdx.x * 128 + threadIdx.x;   // BT*3*WW = 98304
    int w   = gid & (WW - 1);
    int ktb = gid >> 8;
    float* base = g_Sh + (size_t)ktb * NQC * WW + w;
    float v[NQC];
    #pragma unroll
    for (int j = 0; j < NQC; j++) v[j] = base[(size_t)j * WW];
    float s = 0.f;
    #pragma unroll
    for (int j = NQC - 1; j >= 0; j--) {
        base[(size_t)j * WW] = s;
        s += v[j];
    }
}

// =====================================================================
// KS2: in-place exclusive PREFIX sum of g_S3 along qc
// =====================================================================
__global__ void kS2_prefix()
{
    int gid = blockIdx.x * 128 + threadIdx.x;   // BT*WW = 32768
    int w   = gid & (WW - 1);
    int bt  = gid >> 8;
    float* base = g_S3 + (size_t)bt * NQC * WW + w;
    float v[NQC];
    #pragma unroll
    for (int j = 0; j < NQC; j++) v[j] = base[(size_t)j * WW];
    float s = 0.f;
    #pragma unroll
    for (int j = 0; j < NQC; j++) {
        base[(size_t)j * WW] = s;
        s += v[j];
    }
}

// =====================================================================
// K1_FUSED v7: bulk-copy staged x (UBLKCP, 32 x 1KB per row, one thread)
// + mbarrier completion. Alphas in smem (R14-validated). Double-buffered.
// CTA = (quarterchunk, batch), 256 thr = 8 warps = 8 trees.
// One __syncthreads per row. Scans warp-local.
// Emits: cherry -> out, gv2, w1, S3 (raw qc colsums of gv2).
// grid = (NQC, BB) = 1024 CTAs.
// =====================================================================
__global__ void __launch_bounds__(256, 2) k1_fused(const float* __restrict__ x,
                                                   float* __restrict__ out)
{
    extern __shared__ __align__(16) char smem[];
    float* s_x  = (float*)smem;                        // [2][CC][WW]
    u64*   s_al = (u64*)(smem + SMEM_XBUF);            // [T2][CC][6]

    const int tid  = threadIdx.x;
    const int t    = tid >> 5;         // warp = tree
    const int lane = tid & 31;
    const int col  = lane * 8;
    const int qc   = blockIdx.x;
    const int b    = blockIdx.y;
    const int bt   = b * T2 + t;

    const uint32_t s_x_u32  = smem_u32(s_x);
    const uint32_t mbar_u32 = s_x_u32 + SMEM_MBAR;

    // mbarrier init (one per buffer)
    if (tid == 0) {
        MBAR_INIT(mbar_u32,     1);
        MBAR_INIT(mbar_u32 + 8, 1);
    }
    FENCE_PROXY_ASYNC();

    // load alphas for all trees
    for (int i = tid; i < T2 * 6 * CC; i += 256) {
        int f = i % 6, c = (i / 6) % CC, tr = i / (6 * CC);
        s_al[(tr * CC + c) * 6 + f] = g_apk[(tr * 6 + f) * CC + c];
    }

    // ---- init states from suffix-excl Sh (fwd/rev excl scans along w) ----
    float a3[8], p3[8], p2[8], cs[8], incl[8];
    {
        float v[8];
        const size_t sb = ((size_t)bt * 3) * NQC * WW + (size_t)qc * WW + col;
        LD8(v, g_Sh + sb);
        wscan8(v, incl);
        #pragma unroll
        for (int i = 0; i < 8; i++) a3[i] = incl[i] - v[i];
        LD8(v, g_Sh + sb + (size_t)NQC * WW);
        wscan8(v, incl);
        #pragma unroll
        for (int i = 0; i < 8; i++) p3[i] = incl[i] - v[i];
        LD8(v, g_Sh + sb + 2 * (size_t)NQC * WW);
        float tot = wscan8(v, incl);
        #pragma unroll
        for (int i = 0; i < 8; i++) p2[i] = tot - incl[i];
        #pragma unroll
        for (int i = 0; i < 8; i++) cs[i] = 0.f;
    }

    __syncthreads();   // mbarrier init + alpha writes visible

    const char* xg = (const char*)(x + (size_t)b * CC * FIELD);
    // stage row r into buffer bi: 32 bulk copies of 1KB (one per channel)
    auto stage = [&](int r, int bi) {
        const int h = qc * 4 + r;
        const uint32_t mb = mbar_u32 + bi * 8;
        MBAR_EXPECT_TX(mb, (uint32_t)(CC * WW * 4));
        #pragma unroll 8
        for (int c = 0; c < CC; c++) {
            uint32_t dst = s_x_u32 + (uint32_t)(bi * (SMEM_XBUF / 2) + c * (WW * 4));
            const char* src = xg + ((size_t)c * FIELD + (size_t)h * WW) * 4;
            BULK_CP(dst, src, (uint32_t)(WW * 4), mb);
        }
    };

    if (tid == 0) stage(3, 0);

    // ---- 4 rows, bottom-up; k = 3 - r ----
    #pragma unroll 1
    for (int r = 3; r >= 0; r--) {
        const int k = 3 - r;
        __syncthreads();                 // all warps finished previous row
        if (r > 0 && tid == 0) stage(r - 1, (k + 1) & 1);
        MBAR_WAIT(mbar_u32 + (k & 1) * 8, k >> 1);

        const float* sx = s_x + (size_t)(k & 1) * CC * WW + col;
        const int h = qc * 4 + r;

        u64 acc[6][4];
        #pragma unroll
        for (int f = 0; f < 6; f++)
            #pragma unroll
            for (int j = 0; j < 4; j++) acc[f][j] = 0ull;

        const u64* alrow = s_al + (size_t)t * CC * 6;
        #pragma unroll 4
        for (int c = 0; c < CC; c++) {
            float4 v0 = *(const float4*)(sx + c * WW);
            float4 v1 = *(const float4*)(sx + c * WW + 4);
            u64 x01 = pack2(v0.x, v0.y);
            u64 x23 = pack2(v0.z, v0.w);
            u64 x45 = pack2(v1.x, v1.y);
            u64 x67 = pack2(v1.z, v1.w);
            ulonglong2 pA = *(const ulonglong2*)(alrow + c * 6);
            ulonglong2 pB = *(const ulonglong2*)(alrow + c * 6 + 2);
            ulonglong2 pC = *(const ulonglong2*)(alrow + c * 6 + 4);
            acc[0][0] = fma2(x01, pA.x, acc[0][0]);
            acc[0][1] = fma2(x23, pA.x, acc[0][1]);
            acc[0][2] = fma2(x45, pA.x, acc[0][2]);
            acc[0][3] = fma2(x67, pA.x, acc[0][3]);
            acc[1][0] = fma2(x01, pA.y, acc[1][0]);
            acc[1][1] = fma2(x23, pA.y, acc[1][1]);
            acc[1][2] = fma2(x45, pA.y, acc[1][2]);
            acc[1][3] = fma2(x67, pA.y, acc[1][3]);
            acc[2][0] = fma2(x01, pB.x, acc[2][0]);
            acc[2][1] = fma2(x23, pB.x, acc[2][1]);
            acc[2][2] = fma2(x45, pB.x, acc[2][2]);
            acc[2][3] = fma2(x67, pB.x, acc[2][3]);
            acc[3][0] = fma2(x01, pB.y, acc[3][0]);
            acc[3][1] = fma2(x23, pB.y, acc[3][1]);
            acc[3][2] = fma2(x45, pB.y, acc[3][2]);
            acc[3][3] = fma2(x67, pB.y, acc[3][3]);
            acc[4][0] = fma2(x01, pC.x, acc[4][0]);
            acc[4][1] = fma2(x23, pC.x, acc[4][1]);
            acc[4][2] = fma2(x45, pC.x, acc[4][2]);
            acc[4][3] = fma2(x67, pC.x, acc[4][3]);
            acc[5][0] = fma2(x01, pC.y, acc[5][0]);
            acc[5][1] = fma2(x23, pC.y, acc[5][1]);
            acc[5][2] = fma2(x45, pC.y, acc[5][2]);
            acc[5][3] = fma2(x67, pC.y, acc[5][3]);
        }

        const size_t fb = (size_t)bt * FIELD + (size_t)h * WW + col;
        float v[8];

        // gv2 = rev-excl-w-scan(w2 * a3); accumulate colsum
        UNP8(v, acc[1]);
        #pragma unroll
        for (int i = 0; i < 8; i++) v[i] *= a3[i];
        float tot = wscan8(v, incl);
        float gv[8];
        #pragma unroll
        for (int i = 0; i < 8; i++) { gv[i] = tot - incl[i]; cs[i] += gv[i]; }
        ST8(g_gv2 + fb, gv);

        // w1
        UNP8(v, acc[0]);
        ST8(g_w1 + fb, v);

        // cherry = w1p * p3 * p2 (strict-below states)
        UNP8(v, acc[3]);
        #pragma unroll
        for (int i = 0; i < 8; i++) v[i] *= p3[i] * p2[i];
        ST8(out + ((size_t)(b * NT + T2 + t)) * FIELD + (size_t)h * WW + col, v);

        // state updates
        UNP8(v, acc[2]);                    // w3
        wscan8(v, incl);
        #pragma unroll
        for (int i = 0; i < 8; i++) a3[i] += incl[i] - v[i];

        UNP8(v, acc[5]);                    // w3p
        wscan8(v, incl);
        #pragma unroll
        for (int i = 0; i < 8; i++) p3[i] += incl[i] - v[i];

        UNP8(v, acc[4]);                    // w2p
        tot = wscan8(v, incl);
        #pragma unroll
        for (int i = 0; i < 8; i++) p2[i] += tot - incl[i];
    }

    ST8(g_S3 + ((size_t)bt * NQC + qc) * WW + col, cs);
}

// =====================================================================
// KD: top-down. linear = w1 * strict-north colsum of gv2.
// One warp per (qc,t,b) = 8192 warps; init from prefix-excl S3.
// =====================================================================
__global__ void __launch_bounds__(128) kD_topdown(float* __restrict__ out)
{
    const int wid  = threadIdx.x >> 5;
    const int lane = threadIdx.x & 31;
    const int gw   = blockIdx.x * 4 + wid;
    const int qc   =  gw        & 63;
    const int t    = (gw >> 6)  & 7;
    const int b    =  gw >> 9;
    const int bt   = b * T2 + t;
    const int col  = lane * 8;

    float va[8];
    LD8(va, g_S3 + ((size_t)bt * NQC + qc) * WW + col);   // prefix-excl

    const size_t fbase = (size_t)bt * FIELD + (size_t)(qc * 4) * WW + col;
    const size_t obase = ((size_t)(b * NT + t)) * FIELD + (size_t)(qc * 4) * WW + col;

    float w1b[8], gvb[8];
    LD8(w1b, g_w1 + fbase);
    LD8(gvb, g_gv2 + fbase);

    #pragma unroll
    for (int r = 0; r < 4; r++) {
        float w1n[8], gvn[8];
        if (r < 3) {
            LD8(w1n, g_w1  + fbase + (size_t)(r + 1) * WW);
            LD8(gvn, g_gv2 + fbase + (size_t)(r + 1) * WW);
        }
        float o[8];
        #pragma unroll
        for (int i = 0; i < 8; i++) o[i] = w1b[i] * va[i];
        ST8(out + obase + (size_t)r * WW, o);
        #pragma unroll
        for (int i = 0; i < 8; i++) va[i] += gvb[i];
        if (r < 3) {
            #pragma unroll
            for (int i = 0; i < 8; i++) { w1b[i] = w1n[i]; gvb[i] = gvn[i]; }
        }
    }
}

// =====================================================================
extern "C" void kernel_launch(void* const* d_in, const int* in_sizes, int n_in,
                              void* d_out, int out_size)
{
    const float* x   = (const float*)d_in[0];
    const float* a1  = (const float*)d_in[1];
    const float* a2  = (const float*)d_in[2];
    const float* a3  = (const float*)d_in[3];
    const float* a1p = (const float*)d_in[4];
    const float* a2p = (const float*)d_in[5];
    const float* a3p = (const float*)d_in[6];
    float* out = (float*)d_out;

    static bool attr_set = false;
    if (!attr_set) {
        cudaFuncSetAttribute(k1_fused,
                             cudaFuncAttributeMaxDynamicSharedMemorySize, SMEM_K1);
        attr_set = true;
    }

    k0_pack<<<6, 256>>>(a1, a2, a3, a1p, a2p, a3p);

    dim3 gAB(NHC, BB);                          // (32, 16)
    kAB_colsum<<<gAB, 128>>>(x);

    kS_suffix<<<BT * 3 * WW / 128, 128>>>();    // 768 blocks

    dim3 gC(NQC, BB);                           // (64, 16) = 1024 CTAs
    k1_fused<<<gC, 256, SMEM_K1>>>(x, out);

    kS2_prefix<<<BT * WW / 128, 128>>>();       // 256 blocks

    kD_topdown<<<BT * NQC / 4, 128>>>(out);     // 2048 blocks
}

// round 17
// speedup vs baseline: 3.9524x; 1.0659x over previous
#include <cuda_runtime.h>
#include <cstdint>

#define BB   16
#define CC   32
#define HH   256
#define WW   256
#define T2   8
#define NT   16
#define NHC  32               // half-chunks (8 rows)
#define NQC  64               // quarter-chunks (4 rows each)
#define FIELD (HH*WW)
#define BT   (BB*T2)

#define SMEM_XBUF (2*CC*WW*4)             // 65536 B: double-buffered x row tile
#define SMEM_ALPH (T2*CC*6*8)             // 12288 B alphas
#define SMEM_MBAR (SMEM_XBUF + SMEM_ALPH) // mbarriers at 77824
#define SMEM_K1   (SMEM_MBAR + 16)        // 77840 B

typedef unsigned long long u64;

// ---------------- scratch (no cudaMalloc allowed) ----------------
__device__ __align__(256) float g_w1 [BT*FIELD];
__device__ __align__(256) float g_gv2[BT*FIELD];
__device__ __align__(256) float g_Sh [BT*3*NQC*WW];   // qc colsums (w3,w3p,w2p) -> suffix-excl after kS
__device__ __align__(256) float g_S3 [BT*NQC*WW];     // qc colsums of gv2 -> prefix-excl after kS2
__device__ u64 g_apk[T2*6*CC];                        // packed alphas

// ---------------- f32x2 helpers ----------------
__device__ __forceinline__ u64 fma2(u64 a, u64 b, u64 c) {
    u64 d; asm("fma.rn.f32x2 %0, %1, %2, %3;" : "=l"(d) : "l"(a), "l"(b), "l"(c)); return d;
}
__device__ __forceinline__ u64 add2(u64 a, u64 b) {
    u64 d; asm("add.rn.f32x2 %0, %1, %2;" : "=l"(d) : "l"(a), "l"(b)); return d;
}
__device__ __forceinline__ u64 pack2(float lo, float hi) {
    u64 r; asm("mov.b64 %0, {%1, %2};" : "=l"(r) : "f"(lo), "f"(hi)); return r;
}
__device__ __forceinline__ float2 unpack2(u64 v) {
    float2 f; asm("mov.b64 {%0, %1}, %2;" : "=f"(f.x), "=f"(f.y) : "l"(v)); return f;
}
__device__ __forceinline__ void LD8(float* v, const float* p) {
    float4 a = *(const float4*)p, b = *(const float4*)(p + 4);
    v[0]=a.x; v[1]=a.y; v[2]=a.z; v[3]=a.w; v[4]=b.x; v[5]=b.y; v[6]=b.z; v[7]=b.w;
}
__device__ __forceinline__ void ST8(float* p, const float* v) {
    *(float4*)p       = make_float4(v[0],v[1],v[2],v[3]);
    *(float4*)(p + 4) = make_float4(v[4],v[5],v[6],v[7]);
}
__device__ __forceinline__ void UNP8(float* v, const u64* q) {
    #pragma unroll
    for (int j = 0; j < 4; j++) {
        float2 u = unpack2(q[j]); v[2*j] = u.x; v[2*j+1] = u.y;
    }
}

// ---------------- async-bulk + mbarrier helpers ----------------
__device__ __forceinline__ uint32_t smem_u32(const void* p) {
    uint32_t a;
    asm("{ .reg .u64 t; cvta.to.shared.u64 t, %1; cvt.u32.u64 %0, t; }"
        : "=r"(a) : "l"(p));
    return a;
}
#define MBAR_INIT(mbar, cnt) \
    asm volatile("mbarrier.init.shared.b64 [%0], %1;" :: "r"(mbar), "r"(cnt) : "memory")
#define MBAR_EXPECT_TX(mbar, bytes) \
    asm volatile("mbarrier.arrive.expect_tx.shared.b64 _, [%0], %1;" \
                 :: "r"(mbar), "r"(bytes) : "memory")
#define BULK_CP(dst, src, bytes, mbar) \
    asm volatile("cp.async.bulk.shared::cta.global.mbarrier::complete_tx::bytes " \
                 "[%0], [%1], %2, [%3];" \
                 :: "r"(dst), "l"(src), "r"(bytes), "r"(mbar) : "memory")
#define FENCE_PROXY_ASYNC() asm volatile("fence.proxy.async.shared::cta;" ::: "memory")
#define MBAR_WAIT(mbar, parity) do { \
    uint32_t _m = (mbar); uint32_t _p = (parity); uint32_t _done; \
    asm volatile("{\n\t.reg .pred p;\n\t" \
        "mbarrier.try_wait.parity.acquire.cta.shared::cta.b64 p, [%1], %2;\n\t" \
        "selp.b32 %0, 1, 0, p;\n\t}" : "=r"(_done) : "r"(_m), "r"(_p) : "memory"); \
    if (!_done) { \
        asm volatile("{\n\t.reg .pred P1;\n\t" \
            "WAIT_LOOP_%=:\n\t" \
            "mbarrier.try_wait.parity.acquire.cta.shared::cta.b64 P1, [%0], %1, 0x989680;\n\t" \
            "@P1 bra.uni WAIT_DONE_%=;\n\t" \
            "bra.uni WAIT_LOOP_%=;\n\t" \
            "WAIT_DONE_%=:\n\t}" :: "r"(_m), "r"(_p) : "memory"); \
    } \
} while(0)

// ---------------- warp scan: 256 elems, 8 per lane (warp-local) ----------------
__device__ __forceinline__ float wscan8(const float* v, float* incl) {
    float r = 0.f; float tmp[8];
    #pragma unroll
    for (int i = 0; i < 8; i++) { r += v[i]; tmp[i] = r; }
    float s = r;
    const int lane = threadIdx.x & 31;
    #pragma unroll
    for (int d = 1; d < 32; d <<= 1) {
        float n = __shfl_up_sync(0xffffffffu, s, d);
        if (lane >= d) s += n;
    }
    float excl = s - r;
    #pragma unroll
    for (int i = 0; i < 8; i++) incl[i] = tmp[i] + excl;
    return __shfl_sync(0xffffffffu, s, 31);
}

// =====================================================================
// K0: pack alphas duplicated into f32x2 pairs
// field order: 0=a1 1=a2 2=a3 3=a1p 4=a2p 5=a3p
// =====================================================================
__global__ void k0_pack(const float* __restrict__ a1,  const float* __restrict__ a2,
                        const float* __restrict__ a3,  const float* __restrict__ a1p,
                        const float* __restrict__ a2p, const float* __restrict__ a3p)
{
    int i = blockIdx.x * 256 + threadIdx.x;          // T2*6*CC = 1536
    if (i >= T2 * 6 * CC) return;
    int c = i % CC, f = (i / CC) % 6, t = i / (6 * CC);
    const float* p = (f == 0) ? a1 : (f == 1) ? a2 : (f == 2) ? a3
                   : (f == 3) ? a1p : (f == 4) ? a2p : a3p;
    float v = p[t * CC + c];
    g_apk[(t * 6 + f) * CC + c] = pack2(v, v);
}

// =====================================================================
// KAB: raw quarterchunk colsums contracted with alphas (all 8 trees).
// CTA = halfchunk: 2 rowgroups x 64 lanes x float4. grid = (NHC, BB).
// =====================================================================
__global__ void __launch_bounds__(128) kAB_colsum(const float* __restrict__ x)
{
    __shared__ __align__(16) u64 s_alB[CC][24];   // slot = k*8 + t
    const int tid = threadIdx.x;
    const int rg  = tid >> 6;
    const int l   = tid & 63;
    const int hc  = blockIdx.x;
    const int b   = blockIdx.y;
    const int qc  = hc * 2 + rg;
    const int col = l * 4;

    for (int i = tid; i < CC * 24; i += 128) {
        int slot = i % 24, c = i / 24;
        int k = slot / 8, t = slot % 8;
        int f = (k == 0) ? 2 : (k == 1) ? 5 : 4;   // a3, a3p, a2p
        s_alB[c][slot] = g_apk[(t * 6 + f) * CC + c];
    }
    __syncthreads();

    u64 acc[24][2];
    #pragma unroll
    for (int s = 0; s < 24; s++) { acc[s][0] = 0ull; acc[s][1] = 0ull; }

    #pragma unroll 2
    for (int c = 0; c < CC; c++) {
        const float4* xp = (const float4*)(x
            + ((size_t)(b * CC + c) * HH + qc * 4) * WW + col);
        u64 s01 = 0ull, s23 = 0ull;
        #pragma unroll
        for (int r = 0; r < 4; r++) {
            float4 v = xp[r * (WW / 4)];
            s01 = add2(s01, pack2(v.x, v.y));
            s23 = add2(s23, pack2(v.z, v.w));
        }
        #pragma unroll
        for (int j = 0; j < 12; j++) {
            ulonglong2 p = *(const ulonglong2*)&s_alB[c][2 * j];
            acc[2*j][0]   = fma2(s01, p.x, acc[2*j][0]);
            acc[2*j][1]   = fma2(s23, p.x, acc[2*j][1]);
            acc[2*j+1][0] = fma2(s01, p.y, acc[2*j+1][0]);
            acc[2*j+1][1] = fma2(s23, p.y, acc[2*j+1][1]);
        }
    }

    #pragma unroll
    for (int k = 0; k < 3; k++)
        #pragma unroll
        for (int t = 0; t < T2; t++) {
            int s = k * 8 + t;
            float2 v0 = unpack2(acc[s][0]), v1 = unpack2(acc[s][1]);
            size_t o = (((size_t)(b * T2 + t) * 3 + k) * NQC + qc) * WW + col;
            *(float4*)&g_Sh[o] = make_float4(v0.x, v0.y, v1.x, v1.y);
        }
}

// =====================================================================
// KS: in-place exclusive SUFFIX sum of g_Sh along qc (per bt,k,w column)
// =====================================================================
__global__ void kS_suffix()
{
    int gid = blockIdx.x * 128 + threadIdx.x;   // BT*3*WW = 98304
    int w   = gid & (WW - 1);
    int ktb = gid >> 8;
    float* base = g_Sh + (size_t)ktb * NQC * WW + w;
    float v[NQC];
    #pragma unroll
    for (int j = 0; j < NQC; j++) v[j] = base[(size_t)j * WW];
    float s = 0.f;
    #pragma unroll
    for (int j = NQC - 1; j >= 0; j--) {
        base[(size_t)j * WW] = s;
        s += v[j];
    }
}

// =====================================================================
// KS2: in-place exclusive PREFIX sum of g_S3 along qc
// =====================================================================
__global__ void kS2_prefix()
{
    int gid = blockIdx.x * 128 + threadIdx.x;   // BT*WW = 32768
    int w   = gid & (WW - 1);
    int bt  = gid >> 8;
    float* base = g_S3 + (size_t)bt * NQC * WW + w;
    float v[NQC];
    #pragma unroll
    for (int j = 0; j < NQC; j++) v[j] = base[(size_t)j * WW];
    float s = 0.f;
    #pragma unroll
    for (int j = 0; j < NQC; j++) {
        base[(size_t)j * WW] = s;
        s += v[j];
    }
}

// =====================================================================
// K1_FUSED v8: bulk-copy staged x + TWO TREES PER WARP (halves the
// redundant x LDS stream that bound v7 at L1=79%).
// CTA = (quarterchunk, batch), 128 thr = 4 warps x 2 trees, kappa=8.
// Scans warp-local; alphas in smem; 256-reg budget (lb 128,2).
// Emits: cherry -> out, gv2, w1, S3 (raw qc colsums of gv2).
// grid = (NQC, BB) = 1024 CTAs.
// =====================================================================
__global__ void __launch_bounds__(128, 2) k1_fused(const float* __restrict__ x,
                                                   float* __restrict__ out)
{
    extern __shared__ __align__(16) char smem[];
    float* s_x  = (float*)smem;                        // [2][CC][WW]
    u64*   s_al = (u64*)(smem + SMEM_XBUF);            // [T2][CC][6]

    const int tid  = threadIdx.x;
    const int tp   = tid >> 5;         // warp = tree pair {2tp, 2tp+1}
    const int lane = tid & 31;
    const int col  = lane * 8;
    const int qc   = blockIdx.x;
    const int b    = blockIdx.y;
    const int t0   = tp * 2;
    const int bt0  = b * T2 + t0;

    const uint32_t s_x_u32  = smem_u32(s_x);
    const uint32_t mbar_u32 = s_x_u32 + SMEM_MBAR;

    if (tid == 0) {
        MBAR_INIT(mbar_u32,     1);
        MBAR_INIT(mbar_u32 + 8, 1);
    }
    FENCE_PROXY_ASYNC();

    // load alphas for all trees
    for (int i = tid; i < T2 * 6 * CC; i += 128) {
        int f = i % 6, c = (i / 6) % CC, tr = i / (6 * CC);
        s_al[(tr * CC + c) * 6 + f] = g_apk[(tr * 6 + f) * CC + c];
    }

    // ---- init states from suffix-excl Sh (fwd/rev excl scans along w) ----
    float a3[2][8], p3[2][8], p2[2][8], cs[2][8], incl[8];
    #pragma unroll
    for (int tr = 0; tr < 2; tr++) {
        float v[8];
        const size_t sb = ((size_t)(bt0 + tr) * 3) * NQC * WW + (size_t)qc * WW + col;
        LD8(v, g_Sh + sb);
        wscan8(v, incl);
        #pragma unroll
        for (int i = 0; i < 8; i++) a3[tr][i] = incl[i] - v[i];
        LD8(v, g_Sh + sb + (size_t)NQC * WW);
        wscan8(v, incl);
        #pragma unroll
        for (int i = 0; i < 8; i++) p3[tr][i] = incl[i] - v[i];
        LD8(v, g_Sh + sb + 2 * (size_t)NQC * WW);
        float tot = wscan8(v, incl);
        #pragma unroll
        for (int i = 0; i < 8; i++) p2[tr][i] = tot - incl[i];
        #pragma unroll
        for (int i = 0; i < 8; i++) cs[tr][i] = 0.f;
    }

    __syncthreads();   // mbarrier init + alpha writes visible

    const char* xg = (const char*)(x + (size_t)b * CC * FIELD);
    auto stage = [&](int r, int bi) {
        const int h = qc * 4 + r;
        const uint32_t mb = mbar_u32 + bi * 8;
        MBAR_EXPECT_TX(mb, (uint32_t)(CC * WW * 4));
        #pragma unroll 8
        for (int c = 0; c < CC; c++) {
            uint32_t dst = s_x_u32 + (uint32_t)(bi * (SMEM_XBUF / 2) + c * (WW * 4));
            const char* src = xg + ((size_t)c * FIELD + (size_t)h * WW) * 4;
            BULK_CP(dst, src, (uint32_t)(WW * 4), mb);
        }
    };

    if (tid == 0) stage(3, 0);

    // ---- 4 rows, bottom-up; k = 3 - r ----
    #pragma unroll 1
    for (int r = 3; r >= 0; r--) {
        const int k = 3 - r;
        __syncthreads();                 // all warps finished previous row
        if (r > 0 && tid == 0) stage(r - 1, (k + 1) & 1);
        MBAR_WAIT(mbar_u32 + (k & 1) * 8, k >> 1);

        const float* sx = s_x + (size_t)(k & 1) * CC * WW + col;
        const int h = qc * 4 + r;

        u64 acc[2][6][4];
        #pragma unroll
        for (int tr = 0; tr < 2; tr++)
            #pragma unroll
            for (int f = 0; f < 6; f++)
                #pragma unroll
                for (int j = 0; j < 4; j++) acc[tr][f][j] = 0ull;

        const u64* al0 = s_al + (size_t)t0 * CC * 6;
        #pragma unroll 4
        for (int c = 0; c < CC; c++) {
            float4 v0 = *(const float4*)(sx + c * WW);
            float4 v1 = *(const float4*)(sx + c * WW + 4);
            u64 x01 = pack2(v0.x, v0.y);
            u64 x23 = pack2(v0.z, v0.w);
            u64 x45 = pack2(v1.x, v1.y);
            u64 x67 = pack2(v1.z, v1.w);
            #pragma unroll
            for (int tr = 0; tr < 2; tr++) {
                const u64* alrow = al0 + (size_t)tr * CC * 6 + c * 6;
                ulonglong2 pA = *(const ulonglong2*)(alrow);
                ulonglong2 pB = *(const ulonglong2*)(alrow + 2);
                ulonglong2 pC = *(const ulonglong2*)(alrow + 4);
                acc[tr][0][0] = fma2(x01, pA.x, acc[tr][0][0]);
                acc[tr][0][1] = fma2(x23, pA.x, acc[tr][0][1]);
                acc[tr][0][2] = fma2(x45, pA.x, acc[tr][0][2]);
                acc[tr][0][3] = fma2(x67, pA.x, acc[tr][0][3]);
                acc[tr][1][0] = fma2(x01, pA.y, acc[tr][1][0]);
                acc[tr][1][1] = fma2(x23, pA.y, acc[tr][1][1]);
                acc[tr][1][2] = fma2(x45, pA.y, acc[tr][1][2]);
                acc[tr][1][3] = fma2(x67, pA.y, acc[tr][1][3]);
                acc[tr][2][0] = fma2(x01, pB.x, acc[tr][2][0]);
                acc[tr][2][1] = fma2(x23, pB.x, acc[tr][2][1]);
                acc[tr][2][2] = fma2(x45, pB.x, acc[tr][2][2]);
                acc[tr][2][3] = fma2(x67, pB.x, acc[tr][2][3]);
                acc[tr][3][0] = fma2(x01, pB.y, acc[tr][3][0]);
                acc[tr][3][1] = fma2(x23, pB.y, acc[tr][3][1]);
                acc[tr][3][2] = fma2(x45, pB.y, acc[tr][3][2]);
                acc[tr][3][3] = fma2(x67, pB.y, acc[tr][3][3]);
                acc[tr][4][0] = fma2(x01, pC.x, acc[tr][4][0]);
                acc[tr][4][1] = fma2(x23, pC.x, acc[tr][4][1]);
                acc[tr][4][2] = fma2(x45, pC.x, acc[tr][4][2]);
                acc[tr][4][3] = fma2(x67, pC.x, acc[tr][4][3]);
                acc[tr][5][0] = fma2(x01, pC.y, acc[tr][5][0]);
                acc[tr][5][1] = fma2(x23, pC.y, acc[tr][5][1]);
                acc[tr][5][2] = fma2(x45, pC.y, acc[tr][5][2]);
                acc[tr][5][3] = fma2(x67, pC.y, acc[tr][5][3]);
            }
        }

        #pragma unroll
        for (int tr = 0; tr < 2; tr++) {
            const size_t fb = (size_t)(bt0 + tr) * FIELD + (size_t)h * WW + col;
            float v[8];

            // gv2 = rev-excl-w-scan(w2 * a3); accumulate colsum
            UNP8(v, acc[tr][1]);
            #pragma unroll
            for (int i = 0; i < 8; i++) v[i] *= a3[tr][i];
            float tot = wscan8(v, incl);
            float gv[8];
            #pragma unroll
            for (int i = 0; i < 8; i++) { gv[i] = tot - incl[i]; cs[tr][i] += gv[i]; }
            ST8(g_gv2 + fb, gv);

            // w1
            UNP8(v, acc[tr][0]);
            ST8(g_w1 + fb, v);

            // cherry = w1p * p3 * p2 (strict-below states)
            UNP8(v, acc[tr][3]);
            #pragma unroll
            for (int i = 0; i < 8; i++) v[i] *= p3[tr][i] * p2[tr][i];
            ST8(out + ((size_t)(b * NT + T2 + t0 + tr)) * FIELD
                    + (size_t)h * WW + col, v);

            // state updates
            UNP8(v, acc[tr][2]);                    // w3
            wscan8(v, incl);
            #pragma unroll
            for (int i = 0; i < 8; i++) a3[tr][i] += incl[i] - v[i];

            UNP8(v, acc[tr][5]);                    // w3p
            wscan8(v, incl);
            #pragma unroll
            for (int i = 0; i < 8; i++) p3[tr][i] += incl[i] - v[i];

            UNP8(v, acc[tr][4]);                    // w2p
            tot = wscan8(v, incl);
            #pragma unroll
            for (int i = 0; i < 8; i++) p2[tr][i] += tot - incl[i];
        }
    }

    #pragma unroll
    for (int tr = 0; tr < 2; tr++)
        ST8(g_S3 + ((size_t)(bt0 + tr) * NQC + qc) * WW + col, cs[tr]);
}

// =====================================================================
// KD: top-down. linear = w1 * strict-north colsum of gv2.
// One warp per (qc,t,b) = 8192 warps; init from prefix-excl S3.
// =====================================================================
__global__ void __launch_bounds__(128) kD_topdown(float* __restrict__ out)
{
    const int wid  = threadIdx.x >> 5;
    const int lane = threadIdx.x & 31;
    const int gw   = blockIdx.x * 4 + wid;
    const int qc   =  gw        & 63;
    const int t    = (gw >> 6)  & 7;
    const int b    =  gw >> 9;
    const int bt   = b * T2 + t;
    const int col  = lane * 8;

    float va[8];
    LD8(va, g_S3 + ((size_t)bt * NQC + qc) * WW + col);   // prefix-excl

    const size_t fbase = (size_t)bt * FIELD + (size_t)(qc * 4) * WW + col;
    const size_t obase = ((size_t)(b * NT + t)) * FIELD + (size_t)(qc * 4) * WW + col;

    float w1b[8], gvb[8];
    LD8(w1b, g_w1 + fbase);
    LD8(gvb, g_gv2 + fbase);

    #pragma unroll
    for (int r = 0; r < 4; r++) {
        float w1n[8], gvn[8];
        if (r < 3) {
            LD8(w1n, g_w1  + fbase + (size_t)(r + 1) * WW);
            LD8(gvn, g_gv2 + fbase + (size_t)(r + 1) * WW);
        }
        float o[8];
        #pragma unroll
        for (int i = 0; i < 8; i++) o[i] = w1b[i] * va[i];
        ST8(out + obase + (size_t)r * WW, o);
        #pragma unroll
        for (int i = 0; i < 8; i++) va[i] += gvb[i];
        if (r < 3) {
            #pragma unroll
            for (int i = 0; i < 8; i++) { w1b[i] = w1n[i]; gvb[i] = gvn[i]; }
        }
    }
}

// =====================================================================
extern "C" void kernel_launch(void* const* d_in, const int* in_sizes, int n_in,
                              void* d_out, int out_size)
{
    const float* x   = (const float*)d_in[0];
    const float* a1  = (const float*)d_in[1];
    const float* a2  = (const float*)d_in[2];
    const float* a3  = (const float*)d_in[3];
    const float* a1p = (const float*)d_in[4];
    const float* a2p = (const float*)d_in[5];
    const float* a3p = (const float*)d_in[6];
    float* out = (float*)d_out;

    static bool attr_set = false;
    if (!attr_set) {
        cudaFuncSetAttribute(k1_fused,
                             cudaFuncAttributeMaxDynamicSharedMemorySize, SMEM_K1);
        attr_set = true;
    }

    k0_pack<<<6, 256>>>(a1, a2, a3, a1p, a2p, a3p);

    dim3 gAB(NHC, BB);                          // (32, 16)
    kAB_colsum<<<gAB, 128>>>(x);

    kS_suffix<<<BT * 3 * WW / 128, 128>>>();    // 768 blocks

    dim3 gC(NQC, BB);                           // (64, 16) = 1024 CTAs
    k1_fused<<<gC, 128, SMEM_K1>>>(x, out);

    kS2_prefix<<<BT * WW / 128, 128>>>();       // 256 blocks

    kD_topdown<<<BT * NQC / 4, 128>>>(out);     // 2048 blocks
}